// round 7
// baseline (speedup 1.0000x reference)
#include <cuda_runtime.h>
#include <cuda_fp16.h>
#include <cstdint>

// ---------------------------------------------------------------- constants
#define D       512
#define KCAT    1536          // [xh, xh, xl] x [eh, el, eh]  (ll term dropped)
#define N_ROWS  16384
#define K_CB    8192
#define BM      128
#define BN      256
#define KST     64            // k elems per smem stage
#define NSTAGE  (KCAT / KST)  // 24
#define NT      (K_CB / BN)   // 32
#define NBUF    4
#define NTHR    512

// padded row stride = 144 B (ldmatrix conflict-free: 36 words/row)
#define RS           144
#define A_BYTES      (BM * RS)            // 18432
#define B_BYTES      (BN * RS)            // 36864
#define STAGE_BYTES  (A_BYTES + B_BYTES)  // 55296
#define OFF_E2S      (NBUF * STAGE_BYTES) // 221184
#define OFF_CV       (OFF_E2S + 1024)
#define OFF_CI       (OFF_CV + 2048)
#define OFF_BI       (OFF_CI + 2048)
#define SMEM_REQ     (OFF_BI + 512)       // 226816

// ---------------------------------------------------------------- scratch
__device__ __half g_xcat[(size_t)N_ROWS * KCAT];
__device__ __half g_ecat[(size_t)K_CB * KCAT];
__device__ float  g_e2[K_CB];

// ---------------------------------------------------------------- prep
template <int PATTERN>
__global__ void __launch_bounds__(256) catsplit_kernel(const float* __restrict__ in,
                                                       __half* __restrict__ out, int n) {
    int i = blockIdx.x * 256 + threadIdx.x;
    if (i >= n) return;
    int row = i >> 9;
    int c   = i & 511;
    float v = in[i];
    __half h = __float2half_rn(v);
    float hf = __half2float(h);
    __half l = __float2half_rn(v - hf);
    size_t base = (size_t)row * KCAT;
    if (PATTERN == 0) {        // x side: [h, h, l]
        out[base + c]        = h;
        out[base + 512 + c]  = h;
        out[base + 1024 + c] = l;
    } else {                   // codebook side: [h, l, h]
        out[base + c]        = h;
        out[base + 512 + c]  = l;
        out[base + 1024 + c] = h;
    }
}

__global__ void __launch_bounds__(128) e2_kernel(const float* __restrict__ cb) {
    int row = blockIdx.x;
    float4 v = reinterpret_cast<const float4*>(cb + (size_t)row * D)[threadIdx.x];
    float s = v.x * v.x + v.y * v.y + v.z * v.z + v.w * v.w;
    #pragma unroll
    for (int o = 16; o; o >>= 1) s += __shfl_xor_sync(0xffffffffu, s, o);
    __shared__ float ws[4];
    if ((threadIdx.x & 31) == 0) ws[threadIdx.x >> 5] = s;
    __syncthreads();
    if (threadIdx.x == 0) g_e2[row] = ws[0] + ws[1] + ws[2] + ws[3];
}

// ---------------------------------------------------------------- helpers
__device__ __forceinline__ void mma16816(float* c, const uint32_t* a, uint32_t b0, uint32_t b1) {
    asm volatile(
        "mma.sync.aligned.m16n8k16.row.col.f32.f16.f16.f32 "
        "{%0,%1,%2,%3}, {%4,%5,%6,%7}, {%8,%9}, {%0,%1,%2,%3};"
        : "+f"(c[0]), "+f"(c[1]), "+f"(c[2]), "+f"(c[3])
        : "r"(a[0]), "r"(a[1]), "r"(a[2]), "r"(a[3]), "r"(b0), "r"(b1));
}

__device__ __forceinline__ void ldmat4(uint32_t& r0, uint32_t& r1, uint32_t& r2, uint32_t& r3,
                                       uint32_t addr) {
    asm volatile("ldmatrix.sync.aligned.m8n8.x4.shared.b16 {%0,%1,%2,%3}, [%4];"
                 : "=r"(r0), "=r"(r1), "=r"(r2), "=r"(r3) : "r"(addr));
}

__device__ __forceinline__ void cp16(uint32_t dst, const void* src) {
    asm volatile("cp.async.cg.shared.global [%0], [%1], 16;" :: "r"(dst), "l"(src));
}
#define CP_COMMIT() asm volatile("cp.async.commit_group;" ::: "memory")
#define CP_WAIT2()  asm volatile("cp.async.wait_group 2;" ::: "memory")

__device__ __forceinline__ uint32_t smem_u32(const void* p) {
    return (uint32_t)__cvta_generic_to_shared(p);
}

// ---------------------------------------------------------------- main kernel
__global__ void __launch_bounds__(NTHR, 1) vq_kernel(const __half* __restrict__ xcat,
                                                     const __half* __restrict__ ecat,
                                                     const float* __restrict__ e2,
                                                     const float* __restrict__ cb,
                                                     float* __restrict__ out) {
    extern __shared__ char sm[];
    const uint32_t smb = smem_u32(sm);
    const int tid  = threadIdx.x;
    const int lane = tid & 31;
    const int wid  = tid >> 5;
    const int wm   = wid >> 2;        // 0..3 (M, 32 rows each)
    const int wn   = wid & 3;         // 0..3 (N, 64 cols each)
    const int grp  = lane >> 2;       // 0..7
    const int qid  = lane & 3;        // 0..3
    const int rowBase = blockIdx.x * BM;

    float* e2s = (float*)(sm + OFF_E2S);
    float* cv  = (float*)(sm + OFF_CV);
    int*   ci  = (int*)(sm + OFF_CI);

    float runv = 3.4028235e38f;
    int   runi = 0;

    // per-lane ldmatrix address components (hoisted)
    const uint32_t aRow = (uint32_t)(wm * 32 + (lane & 15));          // + mi*16
    const uint32_t aCol = (uint32_t)((lane >> 4) * 16);
    const uint32_t bRow = (uint32_t)(wn * 64 + (lane >> 4) * 8 + (lane & 7)); // + p*16
    const uint32_t bCol = (uint32_t)(((lane >> 3) & 1) * 16);

    auto issue_stage = [&](int g) {
        const int t = g / NSTAGE;
        const int s = g - t * NSTAGE;
        const int d0 = s * KST;
        const int cb0 = t * BN;
        uint32_t A = smb + (g & (NBUF - 1)) * STAGE_BYTES;
        uint32_t B = A + A_BYTES;
        #pragma unroll
        for (int it = 0; it < 2; it++) {
            int id = tid + it * NTHR;         // 0..1023
            int r = id >> 3, c = id & 7;
            cp16(A + r * RS + c * 16, xcat + (size_t)(rowBase + r) * KCAT + d0 + c * 8);
        }
        #pragma unroll
        for (int it = 0; it < 4; it++) {
            int id = tid + it * NTHR;         // 0..2047
            int r = id >> 3, c = id & 7;
            cp16(B + r * RS + c * 16, ecat + (size_t)(cb0 + r) * KCAT + d0 + c * 8);
        }
        CP_COMMIT();
    };

    issue_stage(0); issue_stage(1); issue_stage(2);

    float acc[2][8][4];
    const int S = NT * NSTAGE;                // 768

    for (int g = 0; g < S; g++) {
        const int t = g / NSTAGE;
        const int s = g - t * NSTAGE;

        CP_WAIT2();
        __syncthreads();

        if (s == 0) {
            if (tid < BN) e2s[tid] = e2[t * BN + tid];
            #pragma unroll
            for (int mi = 0; mi < 2; mi++)
                #pragma unroll
                for (int ni = 0; ni < 8; ni++)
                    #pragma unroll
                    for (int j = 0; j < 4; j++) acc[mi][ni][j] = 0.0f;
        }

        // ---- MMA on buffer g%4 (KST=64 -> 4 k-steps of 16)
        {
            uint32_t A = smb + (g & (NBUF - 1)) * STAGE_BYTES;
            uint32_t B = A + A_BYTES;
            #pragma unroll
            for (int kk = 0; kk < 4; kk++) {
                uint32_t a[2][4];
                #pragma unroll
                for (int mi = 0; mi < 2; mi++)
                    ldmat4(a[mi][0], a[mi][1], a[mi][2], a[mi][3],
                           A + (aRow + mi * 16) * RS + kk * 32 + aCol);
                #pragma unroll
                for (int p = 0; p < 4; p++) {
                    uint32_t b0, b1, b2, b3;
                    ldmat4(b0, b1, b2, b3, B + (bRow + p * 16) * RS + kk * 32 + bCol);
                    #pragma unroll
                    for (int mi = 0; mi < 2; mi++) {
                        mma16816(acc[mi][2 * p],     a[mi], b0, b1);
                        mma16816(acc[mi][2 * p + 1], a[mi], b2, b3);
                    }
                }
            }
        }

        // ---- per-tile argmin epilogue at tile end
        if (s == NSTAGE - 1) {
            #pragma unroll
            for (int mi = 0; mi < 2; mi++) {
                #pragma unroll
                for (int h = 0; h < 2; h++) {
                    float v = 3.4028235e38f;
                    int idx = 0;
                    #pragma unroll
                    for (int ni = 0; ni < 8; ni++) {
                        #pragma unroll
                        for (int j = 0; j < 2; j++) {
                            int cl = wn * 64 + ni * 8 + qid * 2 + j;
                            float dd = e2s[cl] - 2.0f * acc[mi][ni][h * 2 + j];
                            if (dd < v) { v = dd; idx = cl; }
                        }
                    }
                    #pragma unroll
                    for (int off = 1; off <= 2; off <<= 1) {
                        float ov = __shfl_xor_sync(0xffffffffu, v, off);
                        int   oi = __shfl_xor_sync(0xffffffffu, idx, off);
                        if (ov < v || (ov == v && oi < idx)) { v = ov; idx = oi; }
                    }
                    if (qid == 0) {
                        int rl = wm * 32 + mi * 16 + grp + h * 8;
                        cv[wn * 128 + rl] = v;
                        ci[wn * 128 + rl] = idx;
                    }
                }
            }
            __syncthreads();
            if (tid < BM) {
                #pragma unroll
                for (int w = 0; w < 4; w++) {
                    float v = cv[w * 128 + tid];
                    int gi = t * BN + ci[w * 128 + tid];
                    if (v < runv || (v == runv && gi < runi)) { runv = v; runi = gi; }
                }
            }
            // next write of cv/ci is a full tile (24 barriers) away
        }

        if (g + NBUF - 1 < S) issue_stage(g + NBUF - 1);
    }

    if (tid < BM) ((int*)(sm + OFF_BI))[tid] = runi;
    __syncthreads();

    // -------- gather: out[row] = cb[best[row]]
    const float4* cb4 = reinterpret_cast<const float4*>(cb);
    float4* out4 = reinterpret_cast<float4*>(out);
    const int* bip = (const int*)(sm + OFF_BI);
    for (int i = tid; i < BM * (D / 4); i += NTHR) {
        int r = i >> 7, c = i & 127;
        out4[(size_t)(rowBase + r) * (D / 4) + c] = cb4[(size_t)bip[r] * (D / 4) + c];
    }
}

// ---------------------------------------------------------------- launch
extern "C" void kernel_launch(void* const* d_in, const int* in_sizes, int n_in,
                              void* d_out, int out_size) {
    const float* x  = (const float*)d_in[0];
    const float* cb = (const float*)d_in[1];
    float* out = (float*)d_out;

    __half *xcat, *ecat;
    float *e2p;
    cudaGetSymbolAddress((void**)&xcat, g_xcat);
    cudaGetSymbolAddress((void**)&ecat, g_ecat);
    cudaGetSymbolAddress((void**)&e2p, g_e2);

    catsplit_kernel<0><<<(N_ROWS * D + 255) / 256, 256>>>(x, xcat, N_ROWS * D);
    catsplit_kernel<1><<<(K_CB * D + 255) / 256, 256>>>(cb, ecat, K_CB * D);
    e2_kernel<<<K_CB, 128>>>(cb);

    cudaFuncSetAttribute(vq_kernel, cudaFuncAttributeMaxDynamicSharedMemorySize, SMEM_REQ);
    vq_kernel<<<N_ROWS / BM, NTHR, SMEM_REQ>>>(xcat, ecat, e2p, cb, out);
}

// round 8
// speedup vs baseline: 1.0015x; 1.0015x over previous
#include <cuda_runtime.h>
#include <cuda_fp16.h>
#include <cstdint>

// ---------------------------------------------------------------- constants
#define D       512
#define KCAT    1536          // [xh, xh, xl] x [eh, el, eh]  (ll term dropped)
#define N_ROWS  16384
#define K_CB    8192
#define BM      128
#define BN      256
#define KST     64            // k elems per smem stage
#define NSTAGE  (KCAT / KST)  // 24
#define NT      (K_CB / BN)   // 32
#define NBUF    4
#define NTHR    512

// padded row stride = 144 B (ldmatrix conflict-free: 36 words/row)
#define RS           144
#define A_BYTES      (BM * RS)            // 18432
#define B_BYTES      (BN * RS)            // 36864
#define STAGE_BYTES  (A_BYTES + B_BYTES)  // 55296
#define OFF_E2S      (NBUF * STAGE_BYTES) // 221184
#define OFF_CV       (OFF_E2S + 1024)
#define OFF_CI       (OFF_CV + 2048)
#define OFF_BI       (OFF_CI + 2048)
#define SMEM_REQ     (OFF_BI + 512)       // 226816

// ---------------------------------------------------------------- scratch
__device__ __half g_xcat[(size_t)N_ROWS * KCAT];
__device__ __half g_ecat[(size_t)K_CB * KCAT];
__device__ float  g_e2[K_CB];

// ---------------------------------------------------------------- prep
template <int PATTERN>
__global__ void __launch_bounds__(256) catsplit_kernel(const float* __restrict__ in,
                                                       __half* __restrict__ out, int n) {
    int i = blockIdx.x * 256 + threadIdx.x;
    if (i >= n) return;
    int row = i >> 9;
    int c   = i & 511;
    float v = in[i];
    __half h = __float2half_rn(v);
    float hf = __half2float(h);
    __half l = __float2half_rn(v - hf);
    size_t base = (size_t)row * KCAT;
    if (PATTERN == 0) {        // x side: [h, h, l]
        out[base + c]        = h;
        out[base + 512 + c]  = h;
        out[base + 1024 + c] = l;
    } else {                   // codebook side: [h, l, h]
        out[base + c]        = h;
        out[base + 512 + c]  = l;
        out[base + 1024 + c] = h;
    }
}

__global__ void __launch_bounds__(128) e2_kernel(const float* __restrict__ cb) {
    int row = blockIdx.x;
    float4 v = reinterpret_cast<const float4*>(cb + (size_t)row * D)[threadIdx.x];
    float s = v.x * v.x + v.y * v.y + v.z * v.z + v.w * v.w;
    #pragma unroll
    for (int o = 16; o; o >>= 1) s += __shfl_xor_sync(0xffffffffu, s, o);
    __shared__ float ws[4];
    if ((threadIdx.x & 31) == 0) ws[threadIdx.x >> 5] = s;
    __syncthreads();
    if (threadIdx.x == 0) g_e2[row] = ws[0] + ws[1] + ws[2] + ws[3];
}

// ---------------------------------------------------------------- helpers
__device__ __forceinline__ void mma16816(float* c, const uint32_t* a, uint32_t b0, uint32_t b1) {
    asm volatile(
        "mma.sync.aligned.m16n8k16.row.col.f32.f16.f16.f32 "
        "{%0,%1,%2,%3}, {%4,%5,%6,%7}, {%8,%9}, {%0,%1,%2,%3};"
        : "+f"(c[0]), "+f"(c[1]), "+f"(c[2]), "+f"(c[3])
        : "r"(a[0]), "r"(a[1]), "r"(a[2]), "r"(a[3]), "r"(b0), "r"(b1));
}

__device__ __forceinline__ void ldmat4(uint32_t& r0, uint32_t& r1, uint32_t& r2, uint32_t& r3,
                                       uint32_t addr) {
    asm volatile("ldmatrix.sync.aligned.m8n8.x4.shared.b16 {%0,%1,%2,%3}, [%4];"
                 : "=r"(r0), "=r"(r1), "=r"(r2), "=r"(r3) : "r"(addr));
}

__device__ __forceinline__ void cp16(uint32_t dst, const void* src) {
    asm volatile("cp.async.cg.shared.global [%0], [%1], 16;" :: "r"(dst), "l"(src));
}
#define CP_COMMIT() asm volatile("cp.async.commit_group;" ::: "memory")
#define CP_WAIT2()  asm volatile("cp.async.wait_group 2;" ::: "memory")

__device__ __forceinline__ uint32_t smem_u32(const void* p) {
    return (uint32_t)__cvta_generic_to_shared(p);
}

// ---------------------------------------------------------------- main kernel
__global__ void __launch_bounds__(NTHR, 1) vq_kernel(const __half* __restrict__ xcat,
                                                     const __half* __restrict__ ecat,
                                                     const float* __restrict__ e2,
                                                     const float* __restrict__ cb,
                                                     float* __restrict__ out) {
    extern __shared__ char sm[];
    const uint32_t smb = smem_u32(sm);
    const int tid  = threadIdx.x;
    const int lane = tid & 31;
    const int wid  = tid >> 5;
    const int wm   = wid >> 2;        // 0..3 (M, 32 rows each)
    const int wn   = wid & 3;         // 0..3 (N, 64 cols each)
    const int grp  = lane >> 2;       // 0..7
    const int qid  = lane & 3;        // 0..3
    const int rowBase = blockIdx.x * BM;

    float* e2s = (float*)(sm + OFF_E2S);
    float* cv  = (float*)(sm + OFF_CV);
    int*   ci  = (int*)(sm + OFF_CI);

    float runv = 3.4028235e38f;
    int   runi = 0;

    // per-lane ldmatrix address components (hoisted)
    const uint32_t aRow = (uint32_t)(wm * 32 + (lane & 15));          // + mi*16
    const uint32_t aCol = (uint32_t)((lane >> 4) * 16);
    const uint32_t bRow = (uint32_t)(wn * 64 + (lane >> 4) * 8 + (lane & 7)); // + p*16
    const uint32_t bCol = (uint32_t)(((lane >> 3) & 1) * 16);

    auto issue_stage = [&](int g) {
        const int t = g / NSTAGE;
        const int s = g - t * NSTAGE;
        const int d0 = s * KST;
        const int cb0 = t * BN;
        uint32_t A = smb + (g & (NBUF - 1)) * STAGE_BYTES;
        uint32_t B = A + A_BYTES;
        #pragma unroll
        for (int it = 0; it < 2; it++) {
            int id = tid + it * NTHR;         // 0..1023
            int r = id >> 3, c = id & 7;
            cp16(A + r * RS + c * 16, xcat + (size_t)(rowBase + r) * KCAT + d0 + c * 8);
        }
        #pragma unroll
        for (int it = 0; it < 4; it++) {
            int id = tid + it * NTHR;         // 0..2047
            int r = id >> 3, c = id & 7;
            cp16(B + r * RS + c * 16, ecat + (size_t)(cb0 + r) * KCAT + d0 + c * 8);
        }
        CP_COMMIT();
    };

    issue_stage(0); issue_stage(1); issue_stage(2);

    float acc[2][8][4];
    const int S = NT * NSTAGE;                // 768

    for (int g = 0; g < S; g++) {
        const int t = g / NSTAGE;
        const int s = g - t * NSTAGE;

        CP_WAIT2();
        __syncthreads();

        if (s == 0) {
            if (tid < BN) e2s[tid] = e2[t * BN + tid];
            #pragma unroll
            for (int mi = 0; mi < 2; mi++)
                #pragma unroll
                for (int ni = 0; ni < 8; ni++)
                    #pragma unroll
                    for (int j = 0; j < 4; j++) acc[mi][ni][j] = 0.0f;
        }

        // ---- MMA on buffer g%4 (KST=64 -> 4 k-steps of 16)
        {
            uint32_t A = smb + (g & (NBUF - 1)) * STAGE_BYTES;
            uint32_t B = A + A_BYTES;
            #pragma unroll
            for (int kk = 0; kk < 4; kk++) {
                uint32_t a[2][4];
                #pragma unroll
                for (int mi = 0; mi < 2; mi++)
                    ldmat4(a[mi][0], a[mi][1], a[mi][2], a[mi][3],
                           A + (aRow + mi * 16) * RS + kk * 32 + aCol);
                #pragma unroll
                for (int p = 0; p < 4; p++) {
                    uint32_t b0, b1, b2, b3;
                    ldmat4(b0, b1, b2, b3, B + (bRow + p * 16) * RS + kk * 32 + bCol);
                    #pragma unroll
                    for (int mi = 0; mi < 2; mi++) {
                        mma16816(acc[mi][2 * p],     a[mi], b0, b1);
                        mma16816(acc[mi][2 * p + 1], a[mi], b2, b3);
                    }
                }
            }
        }

        // ---- per-tile argmin epilogue at tile end
        if (s == NSTAGE - 1) {
            #pragma unroll
            for (int mi = 0; mi < 2; mi++) {
                #pragma unroll
                for (int h = 0; h < 2; h++) {
                    float v = 3.4028235e38f;
                    int idx = 0;
                    #pragma unroll
                    for (int ni = 0; ni < 8; ni++) {
                        #pragma unroll
                        for (int j = 0; j < 2; j++) {
                            int cl = wn * 64 + ni * 8 + qid * 2 + j;
                            float dd = e2s[cl] - 2.0f * acc[mi][ni][h * 2 + j];
                            if (dd < v) { v = dd; idx = cl; }
                        }
                    }
                    #pragma unroll
                    for (int off = 1; off <= 2; off <<= 1) {
                        float ov = __shfl_xor_sync(0xffffffffu, v, off);
                        int   oi = __shfl_xor_sync(0xffffffffu, idx, off);
                        if (ov < v || (ov == v && oi < idx)) { v = ov; idx = oi; }
                    }
                    if (qid == 0) {
                        int rl = wm * 32 + mi * 16 + grp + h * 8;
                        cv[wn * 128 + rl] = v;
                        ci[wn * 128 + rl] = idx;
                    }
                }
            }
            __syncthreads();
            if (tid < BM) {
                #pragma unroll
                for (int w = 0; w < 4; w++) {
                    float v = cv[w * 128 + tid];
                    int gi = t * BN + ci[w * 128 + tid];
                    if (v < runv || (v == runv && gi < runi)) { runv = v; runi = gi; }
                }
            }
            // next write of cv/ci is a full tile (24 barriers) away
        }

        if (g + NBUF - 1 < S) issue_stage(g + NBUF - 1);
    }

    if (tid < BM) ((int*)(sm + OFF_BI))[tid] = runi;
    __syncthreads();

    // -------- gather: out[row] = cb[best[row]]
    const float4* cb4 = reinterpret_cast<const float4*>(cb);
    float4* out4 = reinterpret_cast<float4*>(out);
    const int* bip = (const int*)(sm + OFF_BI);
    for (int i = tid; i < BM * (D / 4); i += NTHR) {
        int r = i >> 7, c = i & 127;
        out4[(size_t)(rowBase + r) * (D / 4) + c] = cb4[(size_t)bip[r] * (D / 4) + c];
    }
}

// ---------------------------------------------------------------- launch
extern "C" void kernel_launch(void* const* d_in, const int* in_sizes, int n_in,
                              void* d_out, int out_size) {
    const float* x  = (const float*)d_in[0];
    const float* cb = (const float*)d_in[1];
    float* out = (float*)d_out;

    __half *xcat, *ecat;
    float *e2p;
    cudaGetSymbolAddress((void**)&xcat, g_xcat);
    cudaGetSymbolAddress((void**)&ecat, g_ecat);
    cudaGetSymbolAddress((void**)&e2p, g_e2);

    catsplit_kernel<0><<<(N_ROWS * D + 255) / 256, 256>>>(x, xcat, N_ROWS * D);
    catsplit_kernel<1><<<(K_CB * D + 255) / 256, 256>>>(cb, ecat, K_CB * D);
    e2_kernel<<<K_CB, 128>>>(cb);

    cudaFuncSetAttribute(vq_kernel, cudaFuncAttributeMaxDynamicSharedMemorySize, SMEM_REQ);
    vq_kernel<<<N_ROWS / BM, NTHR, SMEM_REQ>>>(xcat, ecat, e2p, cb, out);
}

// round 10
// speedup vs baseline: 2.1588x; 2.1556x over previous
#include <cuda_runtime.h>
#include <cuda_fp16.h>
#include <cstdint>

// ---------------------------------------------------------------- constants
#define D       512
#define KCAT3   1536          // [xh, xh, xl] x [eh, el, eh]
#define N_ROWS  16384
#define K_CB    8192
#define BM      128
#define BN      256
#define KST     64
#define NST1    (D / KST)     // 8   (pass 1)
#define NST3    (KCAT3 / KST) // 24  (refine)
#define NT      (K_CB / BN)   // 32
#define NBUF    4
#define NTHR    512
#define CAP     1024          // refine row capacity
#define MARGIN  0.15f

// padded row stride = 144 B (ldmatrix conflict-free)
#define RS           144
#define A_BYTES      (BM * RS)
#define B_BYTES      (BN * RS)
#define STAGE_BYTES  (A_BYTES + B_BYTES)  // 55296
#define OFF_E2S      (NBUF * STAGE_BYTES) // 221184
#define OFF_CV1      (OFF_E2S + 1024)
#define OFF_CI1      (OFF_CV1 + 2048)
#define OFF_CV2      (OFF_CI1 + 2048)
#define OFF_BI       (OFF_CV2 + 2048)
#define SMEM_REQ     (OFF_BI + 512)       // 228864 (< 232448 opt-in)

// ---------------------------------------------------------------- scratch
__device__ __half g_xh[(size_t)N_ROWS * D];
__device__ __half g_eh[(size_t)K_CB * D];
__device__ __half g_ecat3[(size_t)K_CB * KCAT3];
__device__ __half g_xcat3[(size_t)CAP * KCAT3];
__device__ float  g_e2[K_CB];
__device__ int    g_cnt;
__device__ int    g_rows[CAP];
__device__ unsigned long long g_merge[CAP];

// ---------------------------------------------------------------- helpers
__device__ __forceinline__ void mma16816(float* c, const uint32_t* a, uint32_t b0, uint32_t b1) {
    asm volatile(
        "mma.sync.aligned.m16n8k16.row.col.f32.f16.f16.f32 "
        "{%0,%1,%2,%3}, {%4,%5,%6,%7}, {%8,%9}, {%0,%1,%2,%3};"
        : "+f"(c[0]), "+f"(c[1]), "+f"(c[2]), "+f"(c[3])
        : "r"(a[0]), "r"(a[1]), "r"(a[2]), "r"(a[3]), "r"(b0), "r"(b1));
}
__device__ __forceinline__ void ldmat4(uint32_t& r0, uint32_t& r1, uint32_t& r2, uint32_t& r3,
                                       uint32_t addr) {
    asm volatile("ldmatrix.sync.aligned.m8n8.x4.shared.b16 {%0,%1,%2,%3}, [%4];"
                 : "=r"(r0), "=r"(r1), "=r"(r2), "=r"(r3) : "r"(addr));
}
__device__ __forceinline__ void cp16(uint32_t dst, const void* src) {
    asm volatile("cp.async.cg.shared.global [%0], [%1], 16;" :: "r"(dst), "l"(src));
}
#define CP_COMMIT() asm volatile("cp.async.commit_group;" ::: "memory")
#define CP_WAIT2()  asm volatile("cp.async.wait_group 2;" ::: "memory")
__device__ __forceinline__ uint32_t smem_u32(const void* p) {
    return (uint32_t)__cvta_generic_to_shared(p);
}

// ---------------------------------------------------------------- prep
__global__ void __launch_bounds__(128) init_misc() {
    int i = blockIdx.x * 128 + threadIdx.x;
    if (i < CAP) g_merge[i] = ~0ull;
    if (i == 0) g_cnt = 0;
}

__global__ void __launch_bounds__(256) x_prep(const float* __restrict__ x, int n) {
    int i = blockIdx.x * 256 + threadIdx.x;
    if (i < n) g_xh[i] = __float2half_rn(x[i]);
}

__global__ void __launch_bounds__(256) e_prep(const float* __restrict__ cb, int n) {
    int i = blockIdx.x * 256 + threadIdx.x;
    if (i >= n) return;
    int row = i >> 9, c = i & 511;
    float v = cb[i];
    __half h = __float2half_rn(v);
    __half l = __float2half_rn(v - __half2float(h));
    g_eh[i] = h;
    size_t base = (size_t)row * KCAT3;
    g_ecat3[base + c]        = h;
    g_ecat3[base + 512 + c]  = l;
    g_ecat3[base + 1024 + c] = h;
}

__global__ void __launch_bounds__(128) e2_kernel(const float* __restrict__ cb) {
    int row = blockIdx.x;
    float4 v = reinterpret_cast<const float4*>(cb + (size_t)row * D)[threadIdx.x];
    float s = v.x * v.x + v.y * v.y + v.z * v.z + v.w * v.w;
    #pragma unroll
    for (int o = 16; o; o >>= 1) s += __shfl_xor_sync(0xffffffffu, s, o);
    __shared__ float ws[4];
    if ((threadIdx.x & 31) == 0) ws[threadIdx.x >> 5] = s;
    __syncthreads();
    if (threadIdx.x == 0) g_e2[row] = ws[0] + ws[1] + ws[2] + ws[3];
}

// build 3-term x rows for flagged slots
__global__ void __launch_bounds__(64) gather_split(const float* __restrict__ x) {
    int slot = blockIdx.x;
    if (slot >= g_cnt || slot >= CAP) return;
    int row = g_rows[slot];
    size_t base = (size_t)slot * KCAT3;
    for (int c = threadIdx.x; c < D; c += 64) {
        float v = x[(size_t)row * D + c];
        __half h = __float2half_rn(v);
        __half l = __float2half_rn(v - __half2float(h));
        g_xcat3[base + c]        = h;
        g_xcat3[base + 512 + c]  = h;
        g_xcat3[base + 1024 + c] = l;
    }
}

// ---------------------------------------------------------------- pass 1
__global__ void __launch_bounds__(NTHR, 1) pass1_kernel(const float* __restrict__ cb,
                                                        float* __restrict__ out) {
    extern __shared__ char sm[];
    const uint32_t smb = smem_u32(sm);
    const int tid  = threadIdx.x;
    const int lane = tid & 31;
    const int wid  = tid >> 5;
    const int wm   = wid >> 2;
    const int wn   = wid & 3;
    const int grp  = lane >> 2;
    const int qid  = lane & 3;
    const int rowBase = blockIdx.x * BM;

    float* e2s = (float*)(sm + OFF_E2S);
    float* cv1 = (float*)(sm + OFF_CV1);
    int*   ci1 = (int*)(sm + OFF_CI1);
    float* cv2 = (float*)(sm + OFF_CV2);
    int*   bis = (int*)(sm + OFF_BI);

    float rv1 = 3.4028235e38f, rv2 = 3.4028235e38f;
    int   ri1 = 0;

    const uint32_t aRow = (uint32_t)(wm * 32 + (lane & 15));
    const uint32_t aCol = (uint32_t)((lane >> 4) * 16);
    const uint32_t bRow = (uint32_t)(wn * 64 + (lane >> 4) * 8 + (lane & 7));
    const uint32_t bCol = (uint32_t)(((lane >> 3) & 1) * 16);

    auto issue_stage = [&](int g) {
        const int t = g >> 3;               // /NST1
        const int s = g & 7;
        const int d0 = s * KST;
        const int cb0 = t * BN;
        uint32_t A = smb + (g & (NBUF - 1)) * STAGE_BYTES;
        uint32_t B = A + A_BYTES;
        #pragma unroll
        for (int it = 0; it < 2; it++) {
            int id = tid + it * NTHR;
            int r = id >> 3, c = id & 7;
            cp16(A + r * RS + c * 16, g_xh + (size_t)(rowBase + r) * D + d0 + c * 8);
        }
        #pragma unroll
        for (int it = 0; it < 4; it++) {
            int id = tid + it * NTHR;
            int r = id >> 3, c = id & 7;
            cp16(B + r * RS + c * 16, g_eh + (size_t)(cb0 + r) * D + d0 + c * 8);
        }
        CP_COMMIT();
    };

    issue_stage(0); issue_stage(1); issue_stage(2);

    float acc[2][8][4];
    const int S = NT * NST1;                // 256

    for (int g = 0; g < S; g++) {
        const int t = g >> 3;
        const int s = g & 7;

        CP_WAIT2();
        __syncthreads();

        if (s == 0) {
            if (tid < BN) e2s[tid] = g_e2[t * BN + tid];
            #pragma unroll
            for (int mi = 0; mi < 2; mi++)
                #pragma unroll
                for (int ni = 0; ni < 8; ni++)
                    #pragma unroll
                    for (int j = 0; j < 4; j++) acc[mi][ni][j] = 0.0f;
        }

        {
            uint32_t A = smb + (g & (NBUF - 1)) * STAGE_BYTES;
            uint32_t B = A + A_BYTES;
            #pragma unroll
            for (int kk = 0; kk < 4; kk++) {
                uint32_t a[2][4];
                #pragma unroll
                for (int mi = 0; mi < 2; mi++)
                    ldmat4(a[mi][0], a[mi][1], a[mi][2], a[mi][3],
                           A + (aRow + mi * 16) * RS + kk * 32 + aCol);
                #pragma unroll
                for (int p = 0; p < 4; p++) {
                    uint32_t b0, b1, b2, b3;
                    ldmat4(b0, b1, b2, b3, B + (bRow + p * 16) * RS + kk * 32 + bCol);
                    #pragma unroll
                    for (int mi = 0; mi < 2; mi++) {
                        mma16816(acc[mi][2 * p],     a[mi], b0, b1);
                        mma16816(acc[mi][2 * p + 1], a[mi], b2, b3);
                    }
                }
            }
        }

        // ---- per-tile top-2 epilogue
        if (s == NST1 - 1) {
            #pragma unroll
            for (int mi = 0; mi < 2; mi++) {
                #pragma unroll
                for (int h = 0; h < 2; h++) {
                    float v1 = 3.4028235e38f, v2 = 3.4028235e38f;
                    int i1 = 0;
                    #pragma unroll
                    for (int ni = 0; ni < 8; ni++) {
                        #pragma unroll
                        for (int j = 0; j < 2; j++) {
                            int cl = wn * 64 + ni * 8 + qid * 2 + j;
                            float dd = e2s[cl] - 2.0f * acc[mi][ni][h * 2 + j];
                            if (dd < v1) { v2 = v1; v1 = dd; i1 = cl; }
                            else if (dd < v2) v2 = dd;
                        }
                    }
                    #pragma unroll
                    for (int off = 1; off <= 2; off <<= 1) {
                        float w1 = __shfl_xor_sync(0xffffffffu, v1, off);
                        int   j1 = __shfl_xor_sync(0xffffffffu, i1, off);
                        float w2 = __shfl_xor_sync(0xffffffffu, v2, off);
                        if (w1 < v1 || (w1 == v1 && j1 < i1)) {
                            v2 = fminf(v1, w2); v1 = w1; i1 = j1;
                        } else {
                            v2 = fminf(w1, v2);
                        }
                    }
                    if (qid == 0) {
                        int rl = wm * 32 + mi * 16 + grp + h * 8;
                        cv1[wn * 128 + rl] = v1;
                        ci1[wn * 128 + rl] = i1;
                        cv2[wn * 128 + rl] = v2;
                    }
                }
            }
            __syncthreads();
            if (tid < BM) {
                #pragma unroll
                for (int w = 0; w < 4; w++) {
                    float w1 = cv1[w * 128 + tid];
                    int   j1 = t * BN + ci1[w * 128 + tid];
                    float w2 = cv2[w * 128 + tid];
                    if (w1 < rv1 || (w1 == rv1 && j1 < ri1)) {
                        rv2 = fminf(rv1, w2); rv1 = w1; ri1 = j1;
                    } else {
                        rv2 = fminf(w1, rv2);
                    }
                }
            }
        }

        if (g + NBUF - 1 < S) issue_stage(g + NBUF - 1);
    }

    // ---- decide / flag
    if (tid < BM) {
        int b = ri1;
        if (rv2 - rv1 < MARGIN) {
            int pos = atomicAdd(&g_cnt, 1);
            if (pos < CAP) {
                g_rows[pos] = rowBase + tid;
                b = -1;                     // written by refine+scatter
            }
        }
        bis[tid] = b;
    }
    __syncthreads();

    // ---- gather for decided rows
    const float4* cb4 = reinterpret_cast<const float4*>(cb);
    float4* out4 = reinterpret_cast<float4*>(out);
    for (int i = tid; i < BM * (D / 4); i += NTHR) {
        int r = i >> 7, c = i & 127;
        int idx = bis[r];
        if (idx >= 0)
            out4[(size_t)(rowBase + r) * (D / 4) + c] = cb4[(size_t)idx * (D / 4) + c];
    }
}

// ---------------------------------------------------------------- refine (3-term, flagged rows)
__global__ void __launch_bounds__(NTHR, 1) refine_kernel() {
    extern __shared__ char sm[];
    const uint32_t smb = smem_u32(sm);
    const int tid  = threadIdx.x;
    const int lane = tid & 31;
    const int wid  = tid >> 5;
    const int wm   = wid >> 2;
    const int wn   = wid & 3;
    const int grp  = lane >> 2;
    const int qid  = lane & 3;
    const int rb   = blockIdx.x >> 5;     // row block 0..7
    const int t    = blockIdx.x & 31;     // col tile 0..31
    const int slotBase = rb * BM;
    const int cb0 = t * BN;

    float* e2s = (float*)(sm + OFF_E2S);
    float* cv1 = (float*)(sm + OFF_CV1);
    int*   ci1 = (int*)(sm + OFF_CI1);

    const uint32_t aRow = (uint32_t)(wm * 32 + (lane & 15));
    const uint32_t aCol = (uint32_t)((lane >> 4) * 16);
    const uint32_t bRow = (uint32_t)(wn * 64 + (lane >> 4) * 8 + (lane & 7));
    const uint32_t bCol = (uint32_t)(((lane >> 3) & 1) * 16);

    auto issue_stage = [&](int g) {
        const int d0 = g * KST;
        uint32_t A = smb + (g & (NBUF - 1)) * STAGE_BYTES;
        uint32_t B = A + A_BYTES;
        #pragma unroll
        for (int it = 0; it < 2; it++) {
            int id = tid + it * NTHR;
            int r = id >> 3, c = id & 7;
            cp16(A + r * RS + c * 16, g_xcat3 + (size_t)(slotBase + r) * KCAT3 + d0 + c * 8);
        }
        #pragma unroll
        for (int it = 0; it < 4; it++) {
            int id = tid + it * NTHR;
            int r = id >> 3, c = id & 7;
            cp16(B + r * RS + c * 16, g_ecat3 + (size_t)(cb0 + r) * KCAT3 + d0 + c * 8);
        }
        CP_COMMIT();
    };

    issue_stage(0); issue_stage(1); issue_stage(2);

    float acc[2][8][4];
    #pragma unroll
    for (int mi = 0; mi < 2; mi++)
        #pragma unroll
        for (int ni = 0; ni < 8; ni++)
            #pragma unroll
            for (int j = 0; j < 4; j++) acc[mi][ni][j] = 0.0f;

    for (int g = 0; g < NST3; g++) {
        CP_WAIT2();
        __syncthreads();
        if (g == 0 && tid < BN) e2s[tid] = g_e2[cb0 + tid];

        uint32_t A = smb + (g & (NBUF - 1)) * STAGE_BYTES;
        uint32_t B = A + A_BYTES;
        #pragma unroll
        for (int kk = 0; kk < 4; kk++) {
            uint32_t a[2][4];
            #pragma unroll
            for (int mi = 0; mi < 2; mi++)
                ldmat4(a[mi][0], a[mi][1], a[mi][2], a[mi][3],
                       A + (aRow + mi * 16) * RS + kk * 32 + aCol);
            #pragma unroll
            for (int p = 0; p < 4; p++) {
                uint32_t b0, b1, b2, b3;
                ldmat4(b0, b1, b2, b3, B + (bRow + p * 16) * RS + kk * 32 + bCol);
                #pragma unroll
                for (int mi = 0; mi < 2; mi++) {
                    mma16816(acc[mi][2 * p],     a[mi], b0, b1);
                    mma16816(acc[mi][2 * p + 1], a[mi], b2, b3);
                }
            }
        }
        if (g + NBUF - 1 < NST3) issue_stage(g + NBUF - 1);
    }
    __syncthreads();   // e2s visible (covers g==0 load), accs done

    // ---- top-1 epilogue + global merge
    #pragma unroll
    for (int mi = 0; mi < 2; mi++) {
        #pragma unroll
        for (int h = 0; h < 2; h++) {
            float v = 3.4028235e38f;
            int idx = 0;
            #pragma unroll
            for (int ni = 0; ni < 8; ni++) {
                #pragma unroll
                for (int j = 0; j < 2; j++) {
                    int cl = wn * 64 + ni * 8 + qid * 2 + j;
                    float dd = e2s[cl] - 2.0f * acc[mi][ni][h * 2 + j];
                    if (dd < v) { v = dd; idx = cl; }
                }
            }
            #pragma unroll
            for (int off = 1; off <= 2; off <<= 1) {
                float ov = __shfl_xor_sync(0xffffffffu, v, off);
                int   oi = __shfl_xor_sync(0xffffffffu, idx, off);
                if (ov < v || (ov == v && oi < idx)) { v = ov; idx = oi; }
            }
            if (qid == 0) {
                int rl = wm * 32 + mi * 16 + grp + h * 8;
                cv1[wn * 128 + rl] = v;
                ci1[wn * 128 + rl] = idx;
            }
        }
    }
    __syncthreads();
    if (tid < BM) {
        float v = 3.4028235e38f;
        int idx = 0;
        #pragma unroll
        for (int w = 0; w < 4; w++) {
            float ov = cv1[w * 128 + tid];
            int   oi = cb0 + ci1[w * 128 + tid];
            if (ov < v || (ov == v && oi < idx)) { v = ov; idx = oi; }
        }
        uint32_t b = __float_as_uint(v);
        uint32_t key = (b & 0x80000000u) ? ~b : (b | 0x80000000u);
        unsigned long long pk = ((unsigned long long)key << 32) | (uint32_t)idx;
        atomicMin(&g_merge[slotBase + tid], pk);
    }
}

// ---------------------------------------------------------------- scatter
__global__ void __launch_bounds__(128) scatter_kernel(const float* __restrict__ cb,
                                                      float* __restrict__ out) {
    int slot = blockIdx.x;
    int cnt = g_cnt; if (cnt > CAP) cnt = CAP;
    if (slot >= cnt) return;
    int row = g_rows[slot];
    int idx = (int)(uint32_t)(g_merge[slot] & 0xFFFFFFFFull);
    const float4* cb4 = reinterpret_cast<const float4*>(cb);
    float4* out4 = reinterpret_cast<float4*>(out);
    out4[(size_t)row * (D / 4) + threadIdx.x] = cb4[(size_t)idx * (D / 4) + threadIdx.x];
}

// ---------------------------------------------------------------- launch
extern "C" void kernel_launch(void* const* d_in, const int* in_sizes, int n_in,
                              void* d_out, int out_size) {
    const float* x  = (const float*)d_in[0];
    const float* cb = (const float*)d_in[1];
    float* out = (float*)d_out;

    init_misc<<<8, 128>>>();
    x_prep<<<(N_ROWS * D + 255) / 256, 256>>>(x, N_ROWS * D);
    e_prep<<<(K_CB * D + 255) / 256, 256>>>(cb, K_CB * D);
    e2_kernel<<<K_CB, 128>>>(cb);

    cudaFuncSetAttribute(pass1_kernel, cudaFuncAttributeMaxDynamicSharedMemorySize, SMEM_REQ);
    cudaFuncSetAttribute(refine_kernel, cudaFuncAttributeMaxDynamicSharedMemorySize, SMEM_REQ);

    pass1_kernel<<<N_ROWS / BM, NTHR, SMEM_REQ>>>(cb, out);
    gather_split<<<CAP, 64>>>(x);
    refine_kernel<<<(CAP / BM) * NT, NTHR, SMEM_REQ>>>();
    scatter_kernel<<<CAP, 128>>>(cb, out);
}

// round 13
// speedup vs baseline: 2.3426x; 1.0852x over previous
#include <cuda_runtime.h>
#include <cuda_fp16.h>
#include <cstdint>

// ---------------------------------------------------------------- constants
#define D       512
#define KCAT3   1536          // [xh, xh, xl] x [eh, el, eh]
#define N_ROWS  16384
#define K_CB    8192
#define BM      128
#define BN      256
#define KST     64
#define NST1    (D / KST)     // 8   (pass 1)
#define NST3    (KCAT3 / KST) // 24  (refine)
#define NT      (K_CB / BN)   // 32
#define NBUF    4
#define NTHR    512
#define CAP     1024
#define MARGIN  0.15f

// padded row stride = 144 B (ldmatrix conflict-free)
#define RS           144
#define A_BYTES      (BM * RS)
#define B_BYTES      (BN * RS)
#define STAGE_BYTES  (A_BYTES + B_BYTES)  // 55296
#define OFF_E2S      (NBUF * STAGE_BYTES) // 221184
#define OFF_CV1      (OFF_E2S + 1024)
#define OFF_CI1      (OFF_CV1 + 2048)
#define OFF_CV2      (OFF_CI1 + 2048)
#define OFF_BI       (OFF_CV2 + 2048)
#define SMEM_REQ     (OFF_BI + 512)       // 228864

// ---------------------------------------------------------------- scratch
__device__ __half g_xh[(size_t)N_ROWS * D];
__device__ __half g_eh[(size_t)K_CB * D];
__device__ __half g_ecat3[(size_t)K_CB * KCAT3];
__device__ __half g_xcat3[(size_t)CAP * KCAT3];
__device__ float  g_e2[K_CB];
__device__ int    g_cnt;
__device__ int    g_rows[CAP];
__device__ unsigned long long g_merge[CAP];

// ---------------------------------------------------------------- helpers
__device__ __forceinline__ void mma16816(float* c, const uint32_t* a, uint32_t b0, uint32_t b1) {
    asm volatile(
        "mma.sync.aligned.m16n8k16.row.col.f32.f16.f16.f32 "
        "{%0,%1,%2,%3}, {%4,%5,%6,%7}, {%8,%9}, {%0,%1,%2,%3};"
        : "+f"(c[0]), "+f"(c[1]), "+f"(c[2]), "+f"(c[3])
        : "r"(a[0]), "r"(a[1]), "r"(a[2]), "r"(a[3]), "r"(b0), "r"(b1));
}
__device__ __forceinline__ void ldmat4(uint32_t& r0, uint32_t& r1, uint32_t& r2, uint32_t& r3,
                                       uint32_t addr) {
    asm volatile("ldmatrix.sync.aligned.m8n8.x4.shared.b16 {%0,%1,%2,%3}, [%4];"
                 : "=r"(r0), "=r"(r1), "=r"(r2), "=r"(r3) : "r"(addr));
}
__device__ __forceinline__ void cp16(uint32_t dst, const void* src) {
    asm volatile("cp.async.cg.shared.global [%0], [%1], 16;" :: "r"(dst), "l"(src));
}
#define CP_COMMIT() asm volatile("cp.async.commit_group;" ::: "memory")
#define CP_WAIT2()  asm volatile("cp.async.wait_group 2;" ::: "memory")
__device__ __forceinline__ uint32_t smem_u32(const void* p) {
    return (uint32_t)__cvta_generic_to_shared(p);
}

// ---------------------------------------------------------------- prep
__global__ void __launch_bounds__(128) init_misc() {
    int i = blockIdx.x * 128 + threadIdx.x;
    if (i < CAP) g_merge[i] = ~0ull;
    if (i == 0) g_cnt = 0;
}

__global__ void __launch_bounds__(256) x_prep(const float* __restrict__ x, int n4) {
    int i = blockIdx.x * 256 + threadIdx.x;
    if (i >= n4) return;
    float4 v = reinterpret_cast<const float4*>(x)[i];
    __half2 p0 = __floats2half2_rn(v.x, v.y);
    __half2 p1 = __floats2half2_rn(v.z, v.w);
    uint2 pk;
    pk.x = *(uint32_t*)&p0;
    pk.y = *(uint32_t*)&p1;
    reinterpret_cast<uint2*>(g_xh)[i] = pk;
}

// warp-per-row: eh, ecat3 (h,l,h) and e2 in one pass
__global__ void __launch_bounds__(256) e_prep(const float* __restrict__ cb) {
    int row  = blockIdx.x * 8 + (threadIdx.x >> 5);
    int lane = threadIdx.x & 31;
    const float4* src = reinterpret_cast<const float4*>(cb + (size_t)row * D);
    __half* eh  = g_eh + (size_t)row * D;
    __half* ec  = g_ecat3 + (size_t)row * KCAT3;
    float s = 0.0f;
    #pragma unroll
    for (int i = 0; i < 4; i++) {
        int q = lane + i * 32;            // float4 index 0..127
        float4 v = src[q];
        s += v.x * v.x + v.y * v.y + v.z * v.z + v.w * v.w;
        int c = q * 4;
        float f[4] = {v.x, v.y, v.z, v.w};
        #pragma unroll
        for (int j = 0; j < 4; j++) {
            __half h = __float2half_rn(f[j]);
            __half l = __float2half_rn(f[j] - __half2float(h));
            eh[c + j]        = h;
            ec[c + j]        = h;
            ec[512 + c + j]  = l;
            ec[1024 + c + j] = h;
        }
    }
    #pragma unroll
    for (int o = 16; o; o >>= 1) s += __shfl_xor_sync(0xffffffffu, s, o);
    if (lane == 0) g_e2[row] = s;
}

__global__ void __launch_bounds__(64) gather_split(const float* __restrict__ x) {
    int slot = blockIdx.x;
    if (slot >= g_cnt || slot >= CAP) return;
    int row = g_rows[slot];
    size_t base = (size_t)slot * KCAT3;
    for (int c = threadIdx.x; c < D; c += 64) {
        float v = x[(size_t)row * D + c];
        __half h = __float2half_rn(v);
        __half l = __float2half_rn(v - __half2float(h));
        g_xcat3[base + c]        = h;
        g_xcat3[base + 512 + c]  = h;
        g_xcat3[base + 1024 + c] = l;
    }
}

// ---------------------------------------------------------------- pass 1
__global__ void __launch_bounds__(NTHR, 1) pass1_kernel(const float* __restrict__ cb,
                                                        float* __restrict__ out) {
    extern __shared__ char sm[];
    const uint32_t smb = smem_u32(sm);
    const int tid  = threadIdx.x;
    const int lane = tid & 31;
    const int wid  = tid >> 5;
    const int wm   = wid >> 2;
    const int wn   = wid & 3;
    const int grp  = lane >> 2;
    const int qid  = lane & 3;
    const int rowBase = blockIdx.x * BM;

    float* e2s = (float*)(sm + OFF_E2S);
    float* cv1 = (float*)(sm + OFF_CV1);
    int*   ci1 = (int*)(sm + OFF_CI1);
    float* cv2 = (float*)(sm + OFF_CV2);
    int*   bis = (int*)(sm + OFF_BI);

    float rv1 = 3.4028235e38f, rv2 = 3.4028235e38f;
    int   ri1 = 0;

    const uint32_t aRow = (uint32_t)(wm * 32 + (lane & 15));
    const uint32_t aCol = (uint32_t)((lane >> 4) * 16);
    const uint32_t bRow = (uint32_t)(wn * 64 + (lane >> 4) * 8 + (lane & 7));
    const uint32_t bCol = (uint32_t)(((lane >> 3) & 1) * 16);

    auto issue_stage = [&](int g) {
        const int t = g >> 3;               // /NST1
        const int s = g & 7;
        const int d0 = s * KST;
        const int cb0 = t * BN;
        uint32_t A = smb + (g & (NBUF - 1)) * STAGE_BYTES;
        uint32_t B = A + A_BYTES;
        #pragma unroll
        for (int it = 0; it < 2; it++) {
            int id = tid + it * NTHR;
            int r = id >> 3, c = id & 7;
            cp16(A + r * RS + c * 16, g_xh + (size_t)(rowBase + r) * D + d0 + c * 8);
        }
        #pragma unroll
        for (int it = 0; it < 4; it++) {
            int id = tid + it * NTHR;
            int r = id >> 3, c = id & 7;
            cp16(B + r * RS + c * 16, g_eh + (size_t)(cb0 + r) * D + d0 + c * 8);
        }
        CP_COMMIT();
    };

    issue_stage(0); issue_stage(1); issue_stage(2);

    float acc[2][8][4];
    const int S = NT * NST1;                // 256

    for (int g = 0; g < S; g++) {
        const int t = g >> 3;
        const int s = g & 7;

        CP_WAIT2();
        __syncthreads();

        if (s == 0) {
            if (tid < BN) e2s[tid] = g_e2[t * BN + tid];
            #pragma unroll
            for (int mi = 0; mi < 2; mi++)
                #pragma unroll
                for (int ni = 0; ni < 8; ni++)
                    #pragma unroll
                    for (int j = 0; j < 4; j++) acc[mi][ni][j] = 0.0f;
        }

        {
            uint32_t A = smb + (g & (NBUF - 1)) * STAGE_BYTES;
            uint32_t B = A + A_BYTES;
            #pragma unroll
            for (int kk = 0; kk < 4; kk++) {
                uint32_t a[2][4];
                #pragma unroll
                for (int mi = 0; mi < 2; mi++)
                    ldmat4(a[mi][0], a[mi][1], a[mi][2], a[mi][3],
                           A + (aRow + mi * 16) * RS + kk * 32 + aCol);
                #pragma unroll
                for (int p = 0; p < 4; p++) {
                    uint32_t b0, b1, b2, b3;
                    ldmat4(b0, b1, b2, b3, B + (bRow + p * 16) * RS + kk * 32 + bCol);
                    #pragma unroll
                    for (int mi = 0; mi < 2; mi++) {
                        mma16816(acc[mi][2 * p],     a[mi], b0, b1);
                        mma16816(acc[mi][2 * p + 1], a[mi], b2, b3);
                    }
                }
            }
        }

        // ---- per-tile top-2 epilogue
        if (s == NST1 - 1) {
            #pragma unroll
            for (int mi = 0; mi < 2; mi++) {
                #pragma unroll
                for (int h = 0; h < 2; h++) {
                    float v1 = 3.4028235e38f, v2 = 3.4028235e38f;
                    int i1 = 0;
                    #pragma unroll
                    for (int ni = 0; ni < 8; ni++) {
                        #pragma unroll
                        for (int j = 0; j < 2; j++) {
                            int cl = wn * 64 + ni * 8 + qid * 2 + j;
                            float dd = e2s[cl] - 2.0f * acc[mi][ni][h * 2 + j];
                            if (dd < v1) { v2 = v1; v1 = dd; i1 = cl; }
                            else if (dd < v2) v2 = dd;
                        }
                    }
                    #pragma unroll
                    for (int off = 1; off <= 2; off <<= 1) {
                        float w1 = __shfl_xor_sync(0xffffffffu, v1, off);
                        int   j1 = __shfl_xor_sync(0xffffffffu, i1, off);
                        float w2 = __shfl_xor_sync(0xffffffffu, v2, off);
                        if (w1 < v1 || (w1 == v1 && j1 < i1)) {
                            v2 = fminf(v1, w2); v1 = w1; i1 = j1;
                        } else {
                            v2 = fminf(w1, v2);
                        }
                    }
                    if (qid == 0) {
                        int rl = wm * 32 + mi * 16 + grp + h * 8;
                        cv1[wn * 128 + rl] = v1;
                        ci1[wn * 128 + rl] = i1;
                        cv2[wn * 128 + rl] = v2;
                    }
                }
            }
            __syncthreads();
            if (tid < BM) {
                #pragma unroll
                for (int w = 0; w < 4; w++) {
                    float w1 = cv1[w * 128 + tid];
                    int   j1 = t * BN + ci1[w * 128 + tid];
                    float w2 = cv2[w * 128 + tid];
                    if (w1 < rv1 || (w1 == rv1 && j1 < ri1)) {
                        rv2 = fminf(rv1, w2); rv1 = w1; ri1 = j1;
                    } else {
                        rv2 = fminf(w1, rv2);
                    }
                }
            }
        }

        if (g + NBUF - 1 < S) issue_stage(g + NBUF - 1);
    }

    // ---- decide / flag
    if (tid < BM) {
        int b = ri1;
        if (rv2 - rv1 < MARGIN) {
            int pos = atomicAdd(&g_cnt, 1);
            if (pos < CAP) {
                g_rows[pos] = rowBase + tid;
                b = -1;
            }
        }
        bis[tid] = b;
    }
    __syncthreads();

    // ---- gather for decided rows
    const float4* cb4 = reinterpret_cast<const float4*>(cb);
    float4* out4 = reinterpret_cast<float4*>(out);
    for (int i = tid; i < BM * (D / 4); i += NTHR) {
        int r = i >> 7, c = i & 127;
        int idx = bis[r];
        if (idx >= 0)
            out4[(size_t)(rowBase + r) * (D / 4) + c] = cb4[(size_t)idx * (D / 4) + c];
    }
}

// ---------------------------------------------------------------- refine
__global__ void __launch_bounds__(NTHR, 1) refine_kernel() {
    const int rb = blockIdx.x >> 5;       // row block 0..7
    {   // early exit: skip row blocks with no flagged rows
        int cnt = g_cnt; if (cnt > CAP) cnt = CAP;
        if (rb * BM >= cnt) return;
    }
    extern __shared__ char sm[];
    const uint32_t smb = smem_u32(sm);
    const int tid  = threadIdx.x;
    const int lane = tid & 31;
    const int wid  = tid >> 5;
    const int wm   = wid >> 2;
    const int wn   = wid & 3;
    const int grp  = lane >> 2;
    const int qid  = lane & 3;
    const int t    = blockIdx.x & 31;     // col tile
    const int slotBase = rb * BM;
    const int cb0 = t * BN;

    float* e2s = (float*)(sm + OFF_E2S);
    float* cv1 = (float*)(sm + OFF_CV1);
    int*   ci1 = (int*)(sm + OFF_CI1);

    const uint32_t aRow = (uint32_t)(wm * 32 + (lane & 15));
    const uint32_t aCol = (uint32_t)((lane >> 4) * 16);
    const uint32_t bRow = (uint32_t)(wn * 64 + (lane >> 4) * 8 + (lane & 7));
    const uint32_t bCol = (uint32_t)(((lane >> 3) & 1) * 16);

    auto issue_stage = [&](int g) {
        const int d0 = g * KST;
        uint32_t A = smb + (g & (NBUF - 1)) * STAGE_BYTES;
        uint32_t B = A + A_BYTES;
        #pragma unroll
        for (int it = 0; it < 2; it++) {
            int id = tid + it * NTHR;
            int r = id >> 3, c = id & 7;
            cp16(A + r * RS + c * 16, g_xcat3 + (size_t)(slotBase + r) * KCAT3 + d0 + c * 8);
        }
        #pragma unroll
        for (int it = 0; it < 4; it++) {
            int id = tid + it * NTHR;
            int r = id >> 3, c = id & 7;
            cp16(B + r * RS + c * 16, g_ecat3 + (size_t)(cb0 + r) * KCAT3 + d0 + c * 8);
        }
        CP_COMMIT();
    };

    issue_stage(0); issue_stage(1); issue_stage(2);

    float acc[2][8][4];
    #pragma unroll
    for (int mi = 0; mi < 2; mi++)
        #pragma unroll
        for (int ni = 0; ni < 8; ni++)
            #pragma unroll
            for (int j = 0; j < 4; j++) acc[mi][ni][j] = 0.0f;

    for (int g = 0; g < NST3; g++) {
        CP_WAIT2();
        __syncthreads();
        if (g == 0 && tid < BN) e2s[tid] = g_e2[cb0 + tid];

        uint32_t A = smb + (g & (NBUF - 1)) * STAGE_BYTES;
        uint32_t B = A + A_BYTES;
        #pragma unroll
        for (int kk = 0; kk < 4; kk++) {
            uint32_t a[2][4];
            #pragma unroll
            for (int mi = 0; mi < 2; mi++)
                ldmat4(a[mi][0], a[mi][1], a[mi][2], a[mi][3],
                       A + (aRow + mi * 16) * RS + kk * 32 + aCol);
            #pragma unroll
            for (int p = 0; p < 4; p++) {
                uint32_t b0, b1, b2, b3;
                ldmat4(b0, b1, b2, b3, B + (bRow + p * 16) * RS + kk * 32 + bCol);
                #pragma unroll
                for (int mi = 0; mi < 2; mi++) {
                    mma16816(acc[mi][2 * p],     a[mi], b0, b1);
                    mma16816(acc[mi][2 * p + 1], a[mi], b2, b3);
                }
            }
        }
        if (g + NBUF - 1 < NST3) issue_stage(g + NBUF - 1);
    }
    __syncthreads();

    #pragma unroll
    for (int mi = 0; mi < 2; mi++) {
        #pragma unroll
        for (int h = 0; h < 2; h++) {
            float v = 3.4028235e38f;
            int idx = 0;
            #pragma unroll
            for (int ni = 0; ni < 8; ni++) {
                #pragma unroll
                for (int j = 0; j < 2; j++) {
                    int cl = wn * 64 + ni * 8 + qid * 2 + j;
                    float dd = e2s[cl] - 2.0f * acc[mi][ni][h * 2 + j];
                    if (dd < v) { v = dd; idx = cl; }
                }
            }
            #pragma unroll
            for (int off = 1; off <= 2; off <<= 1) {
                float ov = __shfl_xor_sync(0xffffffffu, v, off);
                int   oi = __shfl_xor_sync(0xffffffffu, idx, off);
                if (ov < v || (ov == v && oi < idx)) { v = ov; idx = oi; }
            }
            if (qid == 0) {
                int rl = wm * 32 + mi * 16 + grp + h * 8;
                cv1[wn * 128 + rl] = v;
                ci1[wn * 128 + rl] = idx;
            }
        }
    }
    __syncthreads();
    if (tid < BM) {
        float v = 3.4028235e38f;
        int idx = 0;
        #pragma unroll
        for (int w = 0; w < 4; w++) {
            float ov = cv1[w * 128 + tid];
            int   oi = cb0 + ci1[w * 128 + tid];
            if (ov < v || (ov == v && oi < idx)) { v = ov; idx = oi; }
        }
        uint32_t b = __float_as_uint(v);
        uint32_t key = (b & 0x80000000u) ? ~b : (b | 0x80000000u);
        unsigned long long pk = ((unsigned long long)key << 32) | (uint32_t)idx;
        atomicMin(&g_merge[slotBase + tid], pk);
    }
}

// ---------------------------------------------------------------- scatter
__global__ void __launch_bounds__(128) scatter_kernel(const float* __restrict__ cb,
                                                      float* __restrict__ out) {
    int slot = blockIdx.x;
    int cnt = g_cnt; if (cnt > CAP) cnt = CAP;
    if (slot >= cnt) return;
    int row = g_rows[slot];
    int idx = (int)(uint32_t)(g_merge[slot] & 0xFFFFFFFFull);
    const float4* cb4 = reinterpret_cast<const float4*>(cb);
    float4* out4 = reinterpret_cast<float4*>(out);
    out4[(size_t)row * (D / 4) + threadIdx.x] = cb4[(size_t)idx * (D / 4) + threadIdx.x];
}

// ---------------------------------------------------------------- launch
extern "C" void kernel_launch(void* const* d_in, const int* in_sizes, int n_in,
                              void* d_out, int out_size) {
    const float* x  = (const float*)d_in[0];
    const float* cb = (const float*)d_in[1];
    float* out = (float*)d_out;

    init_misc<<<8, 128>>>();
    x_prep<<<(N_ROWS * D / 4 + 255) / 256, 256>>>(x, N_ROWS * D / 4);
    e_prep<<<K_CB / 8, 256>>>(cb);

    cudaFuncSetAttribute(pass1_kernel, cudaFuncAttributeMaxDynamicSharedMemorySize, SMEM_REQ);
    cudaFuncSetAttribute(refine_kernel, cudaFuncAttributeMaxDynamicSharedMemorySize, SMEM_REQ);

    pass1_kernel<<<N_ROWS / BM, NTHR, SMEM_REQ>>>(cb, out);
    gather_split<<<CAP, 64>>>(x);
    refine_kernel<<<(CAP / BM) * NT, NTHR, SMEM_REQ>>>();
    scatter_kernel<<<CAP, 128>>>(cb, out);
}